// round 14
// baseline (speedup 1.0000x reference)
#include <cuda_runtime.h>
#include <cuda_fp16.h>
#include <cstdint>
#include <cstddef>

// ============================================================================
// W8Linear (harness dtypes: X f32, Wq i32, scale/bias f32, out f32).
//   Y = fp16( fp32(X @ W^T) * scale + bias ),  M=8192, K=4096, N=11008.
// Phase 1: W->fp16 and X->fp16 scratch.
// Phase 2: HMMA GEMM, M128 x N128 x K64, 256 thr (8 warps 2x4, warp 64x32),
//   4-stage cp.async ring, ONE barrier/iter.  MMA uses f16 ACCUMULATE with
//   per-stage (K=64) fp16 chains promoted to fp32 once per iteration
//   (1 ALU op per MMA — R11's 4-op/MMA promote confound removed).
// ============================================================================

#define BM 128
#define BN 128
#define BK 64
#define KSTEPS 64
#define INF 4096
#define OUTF 11008
#define MROWS 8192
#define THREADS 256
#define STAGES 4

// SMEM layout (bytes)
#define ASTAGE 16384
#define BSTAGE 16384
#define SM_A  0
#define SM_B  (STAGES * ASTAGE)                   // 65536
#define SM_SC (SM_B + STAGES * BSTAGE)            // 131072
#define SM_BI (SM_SC + 256)
#define SM_TOTAL (SM_BI + 256)                    // 131584

// fp16 scratch (module-static device memory; not a runtime allocation)
__device__ __align__(16) __half g_Wh[(size_t)OUTF * INF];
__device__ __align__(16) __half g_Xh[(size_t)MROWS * INF];

__device__ __forceinline__ uint32_t swz(uint32_t o) { return o ^ ((o >> 3) & 0x70); }

__device__ __forceinline__ uint32_t s2u(const void* p) {
    return (uint32_t)__cvta_generic_to_shared(p);
}

__device__ __forceinline__ void cp16(uint32_t s, const void* g) {
    asm volatile("cp.async.cg.shared.global [%0], [%1], 16;" :: "r"(s), "l"(g));
}
#define CP_COMMIT() asm volatile("cp.async.commit_group;" ::: "memory")
#define CP_WAIT2()  asm volatile("cp.async.wait_group 2;" ::: "memory")

__device__ __forceinline__ void ldsm4(uint32_t (&r)[4], uint32_t a) {
    asm volatile("ldmatrix.sync.aligned.m8n8.x4.shared.b16 {%0,%1,%2,%3}, [%4];"
                 : "=r"(r[0]), "=r"(r[1]), "=r"(r[2]), "=r"(r[3]) : "r"(a));
}

// f16-accumulate MMA, in-place: {d0,d1} += A*B  (4 halves per thread)
__device__ __forceinline__ void mma_h(uint32_t& d0, uint32_t& d1,
                                      const uint32_t (&a)[4],
                                      uint32_t b0, uint32_t b1) {
    asm volatile("mma.sync.aligned.m16n8k16.row.col.f16.f16.f16.f16 "
                 "{%0,%1}, {%2,%3,%4,%5}, {%6,%7}, {%0,%1};"
                 : "+r"(d0), "+r"(d1)
                 : "r"(a[0]), "r"(a[1]), "r"(a[2]), "r"(a[3]),
                   "r"(b0), "r"(b1));
}

__device__ __forceinline__ uint32_t h2u(__half2 h) {
    return *reinterpret_cast<uint32_t*>(&h);
}

// ---- Phase 1 kernels ----
__global__ void __launch_bounds__(256) cvtW_kernel(const int4* __restrict__ w,
                                                   uint2* __restrict__ o) {
    size_t i = (size_t)blockIdx.x * 256 + threadIdx.x;
    int4 v = w[i];
    uint2 r;
    r.x = h2u(__halves2half2(__int2half_rn(v.x), __int2half_rn(v.y)));
    r.y = h2u(__halves2half2(__int2half_rn(v.z), __int2half_rn(v.w)));
    o[i] = r;
}
__global__ void __launch_bounds__(256) cvtX_kernel(const float4* __restrict__ x,
                                                   uint2* __restrict__ o) {
    size_t i = (size_t)blockIdx.x * 256 + threadIdx.x;
    float4 v = x[i];
    uint2 r;
    r.x = h2u(__floats2half2_rn(v.x, v.y));
    r.y = h2u(__floats2half2_rn(v.z, v.w));
    o[i] = r;
}

// ---- Phase 2: GEMM ----
__global__ void __launch_bounds__(THREADS, 1)
w8lin_kernel(const float* __restrict__ scale, const float* __restrict__ bias,
             float* __restrict__ Y)
{
    extern __shared__ char smem[];
    const uint32_t sb = s2u(smem);
    const int tid = threadIdx.x;
    const int wid = tid >> 5;
    const int lid = tid & 31;
    const int n0 = blockIdx.x * BN;
    const int m0 = blockIdx.y * BM;
    const int m_off = (wid & 1) * 64;   // 2 M-warp groups (warp tile M64)
    const int n_off = (wid >> 1) * 32;  // 4 N-warp groups (warp tile N32)

    if (tid < 128) {
        ((__half*)(smem + SM_SC))[tid] = __float2half_rn(scale[n0 + tid]);
        ((__half*)(smem + SM_BI))[tid] = __float2half_rn(bias[n0 + tid]);
    }

    // ---- stage loaders (cp.async, SW128 rows of 128B; 16KB = 1024 chunks) ----
    auto loadA = [&](int s, int stg) {
        uint32_t base = sb + SM_A + (uint32_t)stg * ASTAGE;
        const __half* g = g_Xh + (size_t)m0 * INF + (size_t)s * BK;
        #pragma unroll
        for (int i = 0; i < 4; i++) {
            int idx = tid + i * THREADS;
            int r = idx >> 3, c = idx & 7;
            cp16(base + swz((uint32_t)(r * 128 + c * 16)),
                 g + (size_t)r * INF + c * 8);
        }
    };
    auto loadB = [&](int s, int stg) {
        uint32_t base = sb + SM_B + (uint32_t)stg * BSTAGE;
        const __half* g = g_Wh + (size_t)n0 * INF + (size_t)s * BK;
        #pragma unroll
        for (int i = 0; i < 4; i++) {
            int idx = tid + i * THREADS;
            int r = idx >> 3, c = idx & 7;
            cp16(base + swz((uint32_t)(r * 128 + c * 16)),
                 g + (size_t)r * INF + c * 8);
        }
    };

    // ---- per-thread ldmatrix byte offsets (pre-swizzle; +kk*32 per k-step) ----
    uint32_t arow[4], brow[2];
    #pragma unroll
    for (int i = 0; i < 4; i++)
        arow[i] = (uint32_t)((m_off + i * 16 + (lid & 15)) * 128 + (lid >> 4) * 16);
    #pragma unroll
    for (int j = 0; j < 2; j++)
        brow[j] = (uint32_t)((n_off + j * 16 + ((lid >> 4) & 1) * 8 + (lid & 7)) * 128
                             + ((lid >> 3) & 1) * 16);

    float acc[4][4][4];
    #pragma unroll
    for (int i = 0; i < 4; i++)
        #pragma unroll
        for (int j = 0; j < 4; j++)
            #pragma unroll
            for (int q = 0; q < 4; q++) acc[i][j][q] = 0.0f;

    auto compute = [&](int stg) {
        uint32_t Ab = sb + SM_A + (uint32_t)stg * ASTAGE;
        uint32_t Bb = sb + SM_B + (uint32_t)stg * BSTAGE;
        uint32_t p[4][4][2];                 // fp16 partials, chained over 4 kk
        #pragma unroll
        for (int i = 0; i < 4; i++)
            #pragma unroll
            for (int j = 0; j < 4; j++) { p[i][j][0] = 0u; p[i][j][1] = 0u; }
        #pragma unroll
        for (int kk = 0; kk < 4; kk++) {
            uint32_t a[4][4], b[2][4];
            #pragma unroll
            for (int i = 0; i < 4; i++) ldsm4(a[i], Ab + swz(arow[i] + kk * 32));
            #pragma unroll
            for (int j = 0; j < 2; j++) ldsm4(b[j], Bb + swz(brow[j] + kk * 32));
            #pragma unroll
            for (int i = 0; i < 4; i++)
                #pragma unroll
                for (int j = 0; j < 2; j++) {
                    mma_h(p[i][2 * j][0],     p[i][2 * j][1],     a[i], b[j][0], b[j][1]);
                    mma_h(p[i][2 * j + 1][0], p[i][2 * j + 1][1], a[i], b[j][2], b[j][3]);
                }
        }
        // promote fp16 partials (K=64 chunk) into fp32 accumulators
        #pragma unroll
        for (int i = 0; i < 4; i++)
            #pragma unroll
            for (int j = 0; j < 4; j++) {
                float2 lo = __half22float2(*reinterpret_cast<__half2*>(&p[i][j][0]));
                float2 hi = __half22float2(*reinterpret_cast<__half2*>(&p[i][j][1]));
                acc[i][j][0] += lo.x; acc[i][j][1] += lo.y;
                acc[i][j][2] += hi.x; acc[i][j][3] += hi.y;
            }
    };

    // ---- prologue: fill 3 stages ----
    #pragma unroll
    for (int s = 0; s < 3; s++) {
        loadA(s, s); loadB(s, s); CP_COMMIT();
    }

    // ---- mainloop: one barrier per iter (4-stage ring; refill targets stage
    //      consumed last iter, protected by this iter's barrier) ----
    for (int s = 0; s < KSTEPS; s++) {
        CP_WAIT2();                 // my chunks of stage s complete
        __syncthreads();            // all warps' chunks of stage s complete
        compute(s & 3);
        if (s + 3 < KSTEPS) {       // refill (s+3)&3 == (s-1)&3 (consumed)
            loadA(s + 3, (s + 3) & 3);
            loadB(s + 3, (s + 3) & 3);
        }
        CP_COMMIT();                // keep group accounting invariant
    }

    // ---- epilogue: fp32 acc -> fp16 round -> *scale + bias (fp16) -> f32 out ----
    const int gid = lid >> 2, tig = lid & 3;
    #pragma unroll
    for (int i = 0; i < 4; i++) {
        const int rbase = m0 + m_off + i * 16 + gid;
        #pragma unroll
        for (int j = 0; j < 4; j++) {
            const int cl = n_off + j * 8 + tig * 2;
            __half2 sc = *(const __half2*)(smem + SM_SC + cl * 2);
            __half2 bi = *(const __half2*)(smem + SM_BI + cl * 2);
            __half2 h01 = __floats2half2_rn(acc[i][j][0], acc[i][j][1]);
            __half2 h23 = __floats2half2_rn(acc[i][j][2], acc[i][j][3]);
            __half2 r01 = __hadd2(__hmul2(h01, sc), bi);
            __half2 r23 = __hadd2(__hmul2(h23, sc), bi);
            *(float2*)(Y + (size_t)rbase * OUTF + n0 + cl) =
                make_float2(__low2float(r01), __high2float(r01));
            *(float2*)(Y + (size_t)(rbase + 8) * OUTF + n0 + cl) =
                make_float2(__low2float(r23), __high2float(r23));
        }
    }
}

extern "C" void kernel_launch(void* const* d_in, const int* in_sizes, int n_in,
                              void* d_out, int out_size) {
    const float* X  = (const float*)d_in[0];
    const int*   Wq = (const int*)d_in[1];
    const float* sc = (const float*)d_in[2];
    const float* bi = (const float*)d_in[3];
    float* Y = (float*)d_out;

    __half* Wh = nullptr;
    __half* Xh = nullptr;
    cudaGetSymbolAddress((void**)&Wh, g_Wh);
    cudaGetSymbolAddress((void**)&Xh, g_Xh);

    // Phase 1: dtype conversion (vectorized, exact-size grids)
    cvtW_kernel<<<(unsigned)((size_t)OUTF * INF / 4 / 256), 256>>>(
        (const int4*)Wq, (uint2*)Wh);
    cvtX_kernel<<<(unsigned)((size_t)MROWS * INF / 4 / 256), 256>>>(
        (const float4*)X, (uint2*)Xh);

    // Phase 2: GEMM
    static bool attr_done = false;
    if (!attr_done) {
        cudaFuncSetAttribute(w8lin_kernel,
                             cudaFuncAttributeMaxDynamicSharedMemorySize, SM_TOTAL);
        attr_done = true;
    }
    dim3 grid(OUTF / BN, MROWS / BM);   // (86, 64)
    w8lin_kernel<<<grid, THREADS, SM_TOTAL>>>(sc, bi, Y);
}

// round 15
// speedup vs baseline: 1.3308x; 1.3308x over previous
#include <cuda_runtime.h>
#include <cuda_fp16.h>
#include <cstdint>
#include <cstddef>

// ============================================================================
// W8Linear (harness dtypes: X f32, Wq i32, scale/bias f32, out f32).
//   Y = fp16( fp32(X @ W^T) * scale + bias ),  M=8192, K=4096, N=11008.
// Phase 1: convert W->fp16, X->fp16 into __device__ scratch.
// Phase 2: pipelined HMMA GEMM (R8 skeleton), M128 x N256 x K64, 256 thr
//   (8 warps 2x4, warp tile 64x64), 4-stage cp.async ring.
//   GRID ORDER SWAPPED to M-fastest: a 148-CTA wave now spans all 64 M-tiles
//   x ~2.3 N-tiles -> working set ~70MB (X 64MB L2-resident + ~5MB W slice)
//   instead of ~146MB (full W per wave) -> GEMM reads come from L2, not DRAM.
// ============================================================================

#define BM 128
#define BN 256
#define BK 64
#define KSTEPS 64
#define INF 4096
#define OUTF 11008
#define MROWS 8192
#define THREADS 256
#define STAGES 4

// SMEM layout (bytes)
#define ASTAGE 16384
#define BSTAGE 32768
#define SM_A  0
#define SM_B  (STAGES * ASTAGE)                   // 65536
#define SM_SC (SM_B + STAGES * BSTAGE)            // 196608
#define SM_BI (SM_SC + 512)
#define SM_TOTAL (SM_BI + 512)                    // 197632

// fp16 scratch (module-static device memory; not a runtime allocation)
__device__ __align__(16) __half g_Wh[(size_t)OUTF * INF];
__device__ __align__(16) __half g_Xh[(size_t)MROWS * INF];

__device__ __forceinline__ uint32_t swz(uint32_t o) { return o ^ ((o >> 3) & 0x70); }

__device__ __forceinline__ uint32_t s2u(const void* p) {
    return (uint32_t)__cvta_generic_to_shared(p);
}

__device__ __forceinline__ void cp16(uint32_t s, const void* g) {
    asm volatile("cp.async.cg.shared.global [%0], [%1], 16;" :: "r"(s), "l"(g));
}
#define CP_COMMIT() asm volatile("cp.async.commit_group;" ::: "memory")
#define CP_WAIT2()  asm volatile("cp.async.wait_group 2;" ::: "memory")

__device__ __forceinline__ void ldsm4(uint32_t (&r)[4], uint32_t a) {
    asm volatile("ldmatrix.sync.aligned.m8n8.x4.shared.b16 {%0,%1,%2,%3}, [%4];"
                 : "=r"(r[0]), "=r"(r[1]), "=r"(r[2]), "=r"(r[3]) : "r"(a));
}

__device__ __forceinline__ void mma16816(float (&d)[4], const uint32_t (&a)[4],
                                         uint32_t b0, uint32_t b1) {
    asm volatile("mma.sync.aligned.m16n8k16.row.col.f32.f16.f16.f32 "
                 "{%0,%1,%2,%3}, {%4,%5,%6,%7}, {%8,%9}, {%0,%1,%2,%3};"
                 : "+f"(d[0]), "+f"(d[1]), "+f"(d[2]), "+f"(d[3])
                 : "r"(a[0]), "r"(a[1]), "r"(a[2]), "r"(a[3]),
                   "r"(b0), "r"(b1));
}

__device__ __forceinline__ uint32_t h2u(__half2 h) {
    return *reinterpret_cast<uint32_t*>(&h);
}

// ---- Phase 1 kernels ----
__global__ void __launch_bounds__(256) cvtW_kernel(const int4* __restrict__ w,
                                                   uint2* __restrict__ o) {
    size_t i = (size_t)blockIdx.x * 256 + threadIdx.x;
    int4 v = w[i];
    uint2 r;
    r.x = h2u(__halves2half2(__int2half_rn(v.x), __int2half_rn(v.y)));
    r.y = h2u(__halves2half2(__int2half_rn(v.z), __int2half_rn(v.w)));
    o[i] = r;
}
__global__ void __launch_bounds__(256) cvtX_kernel(const float4* __restrict__ x,
                                                   uint2* __restrict__ o) {
    size_t i = (size_t)blockIdx.x * 256 + threadIdx.x;
    float4 v = x[i];
    uint2 r;
    r.x = h2u(__floats2half2_rn(v.x, v.y));
    r.y = h2u(__floats2half2_rn(v.z, v.w));
    o[i] = r;
}

// ---- Phase 2: GEMM ----
__global__ void __launch_bounds__(THREADS, 1)
w8lin_kernel(const float* __restrict__ scale, const float* __restrict__ bias,
             float* __restrict__ Y)
{
    extern __shared__ char smem[];
    const uint32_t sb = s2u(smem);
    const int tid = threadIdx.x;
    const int wid = tid >> 5;
    const int lid = tid & 31;
    // M-fastest grid order: x = M-tile, y = N-tile (L2 locality)
    const int m0 = blockIdx.x * BM;
    const int n0 = blockIdx.y * BN;
    const int m_off = (wid & 1) * 64;   // 2 M-warp groups (warp tile M64)
    const int n_off = (wid >> 1) * 64;  // 4 N-warp groups (warp tile N64)

    if (tid < 256) {
        ((__half*)(smem + SM_SC))[tid] = __float2half_rn(scale[n0 + tid]);
        ((__half*)(smem + SM_BI))[tid] = __float2half_rn(bias[n0 + tid]);
    }

    // ---- stage loaders (cp.async, SW128 rows of 128B) ----
    auto loadA = [&](int s, int stg) {
        uint32_t base = sb + SM_A + (uint32_t)stg * ASTAGE;
        const __half* g = g_Xh + (size_t)m0 * INF + (size_t)s * BK;
        #pragma unroll
        for (int i = 0; i < 4; i++) {
            int idx = tid + i * THREADS;
            int r = idx >> 3, c = idx & 7;
            cp16(base + swz((uint32_t)(r * 128 + c * 16)),
                 g + (size_t)r * INF + c * 8);
        }
    };
    auto loadB = [&](int s, int stg) {
        uint32_t base = sb + SM_B + (uint32_t)stg * BSTAGE;
        const __half* g = g_Wh + (size_t)n0 * INF + (size_t)s * BK;
        #pragma unroll
        for (int i = 0; i < 8; i++) {
            int idx = tid + i * THREADS;
            int r = idx >> 3, c = idx & 7;
            cp16(base + swz((uint32_t)(r * 128 + c * 16)),
                 g + (size_t)r * INF + c * 8);
        }
    };

    // ---- per-thread ldmatrix byte offsets (pre-swizzle; +kk*32 per k-step) ----
    uint32_t arow[4], brow[4];
    #pragma unroll
    for (int i = 0; i < 4; i++)
        arow[i] = (uint32_t)((m_off + i * 16 + (lid & 15)) * 128 + (lid >> 4) * 16);
    #pragma unroll
    for (int j = 0; j < 4; j++)
        brow[j] = (uint32_t)((n_off + j * 16 + ((lid >> 4) & 1) * 8 + (lid & 7)) * 128
                             + ((lid >> 3) & 1) * 16);

    float acc[4][8][4];
    #pragma unroll
    for (int i = 0; i < 4; i++)
        #pragma unroll
        for (int j = 0; j < 8; j++)
            #pragma unroll
            for (int q = 0; q < 4; q++) acc[i][j][q] = 0.0f;

    auto compute = [&](int stg) {
        uint32_t Ab = sb + SM_A + (uint32_t)stg * ASTAGE;
        uint32_t Bb = sb + SM_B + (uint32_t)stg * BSTAGE;
        #pragma unroll
        for (int kk = 0; kk < 4; kk++) {
            uint32_t a[4][4], b[4][4];
            #pragma unroll
            for (int i = 0; i < 4; i++) ldsm4(a[i], Ab + swz(arow[i] + kk * 32));
            #pragma unroll
            for (int j = 0; j < 4; j++) ldsm4(b[j], Bb + swz(brow[j] + kk * 32));
            #pragma unroll
            for (int i = 0; i < 4; i++)
                #pragma unroll
                for (int j = 0; j < 4; j++) {
                    mma16816(acc[i][2 * j],     a[i], b[j][0], b[j][1]);
                    mma16816(acc[i][2 * j + 1], a[i], b[j][2], b[j][3]);
                }
        }
    };

    // ---- prologue: fill 3 stages ----
    #pragma unroll
    for (int s = 0; s < 3; s++) {
        loadA(s, s); loadB(s, s); CP_COMMIT();
    }

    // ---- mainloop: one barrier per iter (4-stage ring; refill targets stage
    //      consumed last iter, protected by this iter's barrier) ----
    for (int s = 0; s < KSTEPS; s++) {
        CP_WAIT2();                 // my chunks of stage s complete
        __syncthreads();            // all warps' chunks of stage s complete
        compute(s & 3);
        if (s + 3 < KSTEPS) {       // refill (s+3)&3 == (s-1)&3 (consumed)
            loadA(s + 3, (s + 3) & 3);
            loadB(s + 3, (s + 3) & 3);
        }
        CP_COMMIT();                // keep group accounting invariant
    }

    // ---- epilogue: fp32 acc -> fp16 round -> *scale + bias (fp16) -> f32 out ----
    const int gid = lid >> 2, tig = lid & 3;
    #pragma unroll
    for (int i = 0; i < 4; i++) {
        const int rbase = m0 + m_off + i * 16 + gid;
        #pragma unroll
        for (int j = 0; j < 8; j++) {
            const int cl = n_off + j * 8 + tig * 2;
            __half2 sc = *(const __half2*)(smem + SM_SC + cl * 2);
            __half2 bi = *(const __half2*)(smem + SM_BI + cl * 2);
            __half2 h01 = __floats2half2_rn(acc[i][j][0], acc[i][j][1]);
            __half2 h23 = __floats2half2_rn(acc[i][j][2], acc[i][j][3]);
            __half2 r01 = __hadd2(__hmul2(h01, sc), bi);
            __half2 r23 = __hadd2(__hmul2(h23, sc), bi);
            *(float2*)(Y + (size_t)rbase * OUTF + n0 + cl) =
                make_float2(__low2float(r01), __high2float(r01));
            *(float2*)(Y + (size_t)(rbase + 8) * OUTF + n0 + cl) =
                make_float2(__low2float(r23), __high2float(r23));
        }
    }
}

extern "C" void kernel_launch(void* const* d_in, const int* in_sizes, int n_in,
                              void* d_out, int out_size) {
    const float* X  = (const float*)d_in[0];
    const int*   Wq = (const int*)d_in[1];
    const float* sc = (const float*)d_in[2];
    const float* bi = (const float*)d_in[3];
    float* Y = (float*)d_out;

    __half* Wh = nullptr;
    __half* Xh = nullptr;
    cudaGetSymbolAddress((void**)&Wh, g_Wh);
    cudaGetSymbolAddress((void**)&Xh, g_Xh);

    // Phase 1: dtype conversion (vectorized, exact-size grids)
    cvtW_kernel<<<(unsigned)((size_t)OUTF * INF / 4 / 256), 256>>>(
        (const int4*)Wq, (uint2*)Wh);
    cvtX_kernel<<<(unsigned)((size_t)MROWS * INF / 4 / 256), 256>>>(
        (const float4*)X, (uint2*)Xh);

    // Phase 2: GEMM (M-fastest grid order for L2 residency)
    static bool attr_done = false;
    if (!attr_done) {
        cudaFuncSetAttribute(w8lin_kernel,
                             cudaFuncAttributeMaxDynamicSharedMemorySize, SM_TOTAL);
        attr_done = true;
    }
    dim3 grid(MROWS / BM, OUTF / BN);   // (64, 43)  x = M-tile (fastest)
    w8lin_kernel<<<grid, THREADS, SM_TOTAL>>>(sc, bi, Y);
}

// round 16
// speedup vs baseline: 1.3421x; 1.0084x over previous
#include <cuda_runtime.h>
#include <cuda_fp16.h>
#include <cstdint>
#include <cstddef>

// ============================================================================
// W8Linear (harness dtypes: X f32, Wq i32, scale/bias f32, out f32).
//   Y = fp16( fp32(X @ W^T) * scale + bias ),  M=8192, K=4096, N=11008.
// Converged design: GEMM is at the mma.sync HMMA issue ceiling (measured
// 10.0 cyc/HMMA/SMSP invariant across 5 structural variants); conversions
// are DRAM-bound. This round fuses the two conversion kernels into one
// launch with 16B stores (last shavable overhead).
// ============================================================================

#define BM 128
#define BN 256
#define BK 64
#define KSTEPS 64
#define INF 4096
#define OUTF 11008
#define MROWS 8192
#define THREADS 256
#define STAGES 4

// SMEM layout (bytes)
#define ASTAGE 16384
#define BSTAGE 32768
#define SM_A  0
#define SM_B  (STAGES * ASTAGE)                   // 65536
#define SM_SC (SM_B + STAGES * BSTAGE)            // 196608
#define SM_BI (SM_SC + 512)
#define SM_TOTAL (SM_BI + 512)                    // 197632

// conversion grid split: W first, then X
#define WBLOCKS 22016u    // (11008*4096/8)/256
#define XBLOCKS 16384u    // (8192*4096/8)/256

// fp16 scratch (module-static device memory; not a runtime allocation)
__device__ __align__(16) __half g_Wh[(size_t)OUTF * INF];
__device__ __align__(16) __half g_Xh[(size_t)MROWS * INF];

__device__ __forceinline__ uint32_t swz(uint32_t o) { return o ^ ((o >> 3) & 0x70); }

__device__ __forceinline__ uint32_t s2u(const void* p) {
    return (uint32_t)__cvta_generic_to_shared(p);
}

__device__ __forceinline__ void cp16(uint32_t s, const void* g) {
    asm volatile("cp.async.cg.shared.global [%0], [%1], 16;" :: "r"(s), "l"(g));
}
#define CP_COMMIT() asm volatile("cp.async.commit_group;" ::: "memory")
#define CP_WAIT2()  asm volatile("cp.async.wait_group 2;" ::: "memory")

__device__ __forceinline__ void ldsm4(uint32_t (&r)[4], uint32_t a) {
    asm volatile("ldmatrix.sync.aligned.m8n8.x4.shared.b16 {%0,%1,%2,%3}, [%4];"
                 : "=r"(r[0]), "=r"(r[1]), "=r"(r[2]), "=r"(r[3]) : "r"(a));
}

__device__ __forceinline__ void mma16816(float (&d)[4], const uint32_t (&a)[4],
                                         uint32_t b0, uint32_t b1) {
    asm volatile("mma.sync.aligned.m16n8k16.row.col.f32.f16.f16.f32 "
                 "{%0,%1,%2,%3}, {%4,%5,%6,%7}, {%8,%9}, {%0,%1,%2,%3};"
                 : "+f"(d[0]), "+f"(d[1]), "+f"(d[2]), "+f"(d[3])
                 : "r"(a[0]), "r"(a[1]), "r"(a[2]), "r"(a[3]),
                   "r"(b0), "r"(b1));
}

__device__ __forceinline__ uint32_t h2u(__half2 h) {
    return *reinterpret_cast<uint32_t*>(&h);
}

// ---- Phase 1: fused W(int32->fp16) + X(f32->fp16), 16B stores ----
__device__ __forceinline__ uint32_t packi(int lo, int hi) {
    return h2u(__halves2half2(__int2half_rn(lo), __int2half_rn(hi)));
}
__global__ void __launch_bounds__(256) cvt_fused_kernel(
    const int4* __restrict__ w, uint4* __restrict__ wo,
    const float4* __restrict__ x, uint4* __restrict__ xo)
{
    const uint32_t b = blockIdx.x;
    if (b < WBLOCKS) {
        size_t i = (size_t)b * 256 + threadIdx.x;    // 8 ints -> 16B fp16
        int4 a = w[2 * i], c = w[2 * i + 1];
        uint4 r;
        r.x = packi(a.x, a.y); r.y = packi(a.z, a.w);
        r.z = packi(c.x, c.y); r.w = packi(c.z, c.w);
        wo[i] = r;
    } else {
        size_t i = (size_t)(b - WBLOCKS) * 256 + threadIdx.x;  // 8 floats -> 16B
        float4 a = x[2 * i], c = x[2 * i + 1];
        uint4 r;
        r.x = h2u(__floats2half2_rn(a.x, a.y));
        r.y = h2u(__floats2half2_rn(a.z, a.w));
        r.z = h2u(__floats2half2_rn(c.x, c.y));
        r.w = h2u(__floats2half2_rn(c.z, c.w));
        xo[i] = r;
    }
}

// ---- Phase 2: GEMM (R8 config — at the HMMA issue ceiling) ----
__global__ void __launch_bounds__(THREADS, 1)
w8lin_kernel(const float* __restrict__ scale, const float* __restrict__ bias,
             float* __restrict__ Y)
{
    extern __shared__ char smem[];
    const uint32_t sb = s2u(smem);
    const int tid = threadIdx.x;
    const int wid = tid >> 5;
    const int lid = tid & 31;
    const int n0 = blockIdx.x * BN;
    const int m0 = blockIdx.y * BM;
    const int m_off = (wid & 1) * 64;   // 2 M-warp groups (warp tile M64)
    const int n_off = (wid >> 1) * 64;  // 4 N-warp groups (warp tile N64)

    if (tid < 256) {
        ((__half*)(smem + SM_SC))[tid] = __float2half_rn(scale[n0 + tid]);
        ((__half*)(smem + SM_BI))[tid] = __float2half_rn(bias[n0 + tid]);
    }

    // ---- stage loaders (cp.async, SW128 rows of 128B) ----
    auto loadA = [&](int s, int stg) {
        uint32_t base = sb + SM_A + (uint32_t)stg * ASTAGE;
        const __half* g = g_Xh + (size_t)m0 * INF + (size_t)s * BK;
        #pragma unroll
        for (int i = 0; i < 4; i++) {
            int idx = tid + i * THREADS;
            int r = idx >> 3, c = idx & 7;
            cp16(base + swz((uint32_t)(r * 128 + c * 16)),
                 g + (size_t)r * INF + c * 8);
        }
    };
    auto loadB = [&](int s, int stg) {
        uint32_t base = sb + SM_B + (uint32_t)stg * BSTAGE;
        const __half* g = g_Wh + (size_t)n0 * INF + (size_t)s * BK;
        #pragma unroll
        for (int i = 0; i < 8; i++) {
            int idx = tid + i * THREADS;
            int r = idx >> 3, c = idx & 7;
            cp16(base + swz((uint32_t)(r * 128 + c * 16)),
                 g + (size_t)r * INF + c * 8);
        }
    };

    // ---- per-thread ldmatrix byte offsets (pre-swizzle; +kk*32 per k-step) ----
    uint32_t arow[4], brow[4];
    #pragma unroll
    for (int i = 0; i < 4; i++)
        arow[i] = (uint32_t)((m_off + i * 16 + (lid & 15)) * 128 + (lid >> 4) * 16);
    #pragma unroll
    for (int j = 0; j < 4; j++)
        brow[j] = (uint32_t)((n_off + j * 16 + ((lid >> 4) & 1) * 8 + (lid & 7)) * 128
                             + ((lid >> 3) & 1) * 16);

    float acc[4][8][4];
    #pragma unroll
    for (int i = 0; i < 4; i++)
        #pragma unroll
        for (int j = 0; j < 8; j++)
            #pragma unroll
            for (int q = 0; q < 4; q++) acc[i][j][q] = 0.0f;

    auto compute = [&](int stg) {
        uint32_t Ab = sb + SM_A + (uint32_t)stg * ASTAGE;
        uint32_t Bb = sb + SM_B + (uint32_t)stg * BSTAGE;
        #pragma unroll
        for (int kk = 0; kk < 4; kk++) {
            uint32_t a[4][4], b[4][4];
            #pragma unroll
            for (int i = 0; i < 4; i++) ldsm4(a[i], Ab + swz(arow[i] + kk * 32));
            #pragma unroll
            for (int j = 0; j < 4; j++) ldsm4(b[j], Bb + swz(brow[j] + kk * 32));
            #pragma unroll
            for (int i = 0; i < 4; i++)
                #pragma unroll
                for (int j = 0; j < 4; j++) {
                    mma16816(acc[i][2 * j],     a[i], b[j][0], b[j][1]);
                    mma16816(acc[i][2 * j + 1], a[i], b[j][2], b[j][3]);
                }
        }
    };

    // ---- prologue: fill 3 stages ----
    #pragma unroll
    for (int s = 0; s < 3; s++) {
        loadA(s, s); loadB(s, s); CP_COMMIT();
    }

    // ---- mainloop: one barrier per iter (4-stage ring; refill targets stage
    //      consumed last iter, protected by this iter's barrier) ----
    for (int s = 0; s < KSTEPS; s++) {
        CP_WAIT2();                 // my chunks of stage s complete
        __syncthreads();            // all warps' chunks of stage s complete
        compute(s & 3);
        if (s + 3 < KSTEPS) {       // refill (s+3)&3 == (s-1)&3 (consumed)
            loadA(s + 3, (s + 3) & 3);
            loadB(s + 3, (s + 3) & 3);
        }
        CP_COMMIT();                // keep group accounting invariant
    }

    // ---- epilogue: fp32 acc -> fp16 round -> *scale + bias (fp16) -> f32 out ----
    const int gid = lid >> 2, tig = lid & 3;
    #pragma unroll
    for (int i = 0; i < 4; i++) {
        const int rbase = m0 + m_off + i * 16 + gid;
        #pragma unroll
        for (int j = 0; j < 8; j++) {
            const int cl = n_off + j * 8 + tig * 2;
            __half2 sc = *(const __half2*)(smem + SM_SC + cl * 2);
            __half2 bi = *(const __half2*)(smem + SM_BI + cl * 2);
            __half2 h01 = __floats2half2_rn(acc[i][j][0], acc[i][j][1]);
            __half2 h23 = __floats2half2_rn(acc[i][j][2], acc[i][j][3]);
            __half2 r01 = __hadd2(__hmul2(h01, sc), bi);
            __half2 r23 = __hadd2(__hmul2(h23, sc), bi);
            *(float2*)(Y + (size_t)rbase * OUTF + n0 + cl) =
                make_float2(__low2float(r01), __high2float(r01));
            *(float2*)(Y + (size_t)(rbase + 8) * OUTF + n0 + cl) =
                make_float2(__low2float(r23), __high2float(r23));
        }
    }
}

extern "C" void kernel_launch(void* const* d_in, const int* in_sizes, int n_in,
                              void* d_out, int out_size) {
    const float* X  = (const float*)d_in[0];
    const int*   Wq = (const int*)d_in[1];
    const float* sc = (const float*)d_in[2];
    const float* bi = (const float*)d_in[3];
    float* Y = (float*)d_out;

    __half* Wh = nullptr;
    __half* Xh = nullptr;
    cudaGetSymbolAddress((void**)&Wh, g_Wh);
    cudaGetSymbolAddress((void**)&Xh, g_Xh);

    // Phase 1: fused dtype conversion (one launch, 16B stores)
    cvt_fused_kernel<<<WBLOCKS + XBLOCKS, 256>>>(
        (const int4*)Wq, (uint4*)Wh, (const float4*)X, (uint4*)Xh);

    // Phase 2: GEMM
    static bool attr_done = false;
    if (!attr_done) {
        cudaFuncSetAttribute(w8lin_kernel,
                             cudaFuncAttributeMaxDynamicSharedMemorySize, SM_TOTAL);
        attr_done = true;
    }
    dim3 grid(OUTF / BN, MROWS / BM);   // (43, 64)
    w8lin_kernel<<<grid, THREADS, SM_TOTAL>>>(sc, bi, Y);
}